// round 1
// baseline (speedup 1.0000x reference)
#include <cuda_runtime.h>
#include <math.h>

#define BB 16
#define TT 77
#define SSRC 300
#define NHID 300
#define LL 677
#define DM 512
#define NH 8
#define HD 64
#define TOKS 10832   // 16*77 + 16*300 + 16*300

// ----- scratch arena (floats) -----
#define OFF_ST    0L
#define OFF_ADA   8192L         // 3*16*3072 = 147456
#define OFF_NBUF  155648L       // TOKS*512
#define OFF_QKV   5701632L      // 3 * TOKS*512
#define OFF_QA    22339584L     // [B,H,L,64]
#define OFF_KA    27885568L
#define OFF_VA    33431552L
#define OFF_OGAT  38977536L     // gathered attn out, token-major [TOKS,512]
#define OFF_ABUF  44523520L
#define OFF_HBUF  50069504L
#define OFF_N2    55615488L
#define OFF_U     61161472L     // TOKS*4096
#define OFF_G     105529344L    // TOKS*2048
#define OFF_FF    127713280L
#define ARENA_SZ  133259264L

__device__ float d_arena[ARENA_SZ];

// ---------------------------------------------------------------------------
// silu(temb) -> st
__global__ void k_silu(const float* __restrict__ temb) {
    int i = blockIdx.x * blockDim.x + threadIdx.x;
    if (i < BB * DM) {
        float v = temb[i];
        d_arena[OFF_ST + i] = v / (1.f + __expf(-v));
    }
}

// ---------------------------------------------------------------------------
// generic fp32 GEMM: C = A @ B + bias.  A rows live in the arena (offA),
// B/bias are external pointers, C in arena (offC).  blockIdx.z batches B/bias/C.
__global__ void k_gemm(const float* __restrict__ Bmat, const float* __restrict__ bias,
                       long offA, long offC, int M, int N, int K,
                       long szB, long szBias, long szC) {
    const float* A  = d_arena + offA;
    const float* Bm = Bmat + (long)blockIdx.z * szB;
    const float* bi = bias + (long)blockIdx.z * szBias;
    float*       C  = d_arena + offC + (long)blockIdx.z * szC;

    __shared__ float As[16][68];
    __shared__ float Bs[16][64];

    int tid = threadIdx.x;
    int tx = tid & 15, ty = tid >> 4;

    int arow = tid >> 2;           // 0..63
    int akc  = (tid & 3) << 2;     // 0,4,8,12
    int brow = tid >> 4;           // 0..15
    int bcol = (tid & 15) << 2;    // 0..60

    long grow  = (long)blockIdx.y * 64 + arow;
    int  gcolB = blockIdx.x * 64 + bcol;

    float acc[4][4];
#pragma unroll
    for (int i = 0; i < 4; i++)
#pragma unroll
        for (int j = 0; j < 4; j++) acc[i][j] = 0.f;

    for (int kt = 0; kt < K; kt += 16) {
        float4 a4 = make_float4(0.f, 0.f, 0.f, 0.f);
        if (grow < M) a4 = *(const float4*)&A[grow * K + kt + akc];
        As[akc + 0][arow] = a4.x;
        As[akc + 1][arow] = a4.y;
        As[akc + 2][arow] = a4.z;
        As[akc + 3][arow] = a4.w;

        float4 b4 = *(const float4*)&Bm[(long)(kt + brow) * N + gcolB];
        *(float4*)&Bs[brow][bcol] = b4;
        __syncthreads();

#pragma unroll
        for (int k = 0; k < 16; k++) {
            float4 av = *(const float4*)&As[k][ty << 2];
            float4 bv = *(const float4*)&Bs[k][tx << 2];
            float a[4] = {av.x, av.y, av.z, av.w};
            float b[4] = {bv.x, bv.y, bv.z, bv.w};
#pragma unroll
            for (int i = 0; i < 4; i++)
#pragma unroll
                for (int j = 0; j < 4; j++) acc[i][j] += a[i] * b[j];
        }
        __syncthreads();
    }

    int crow0 = blockIdx.y * 64 + (ty << 2);
    int ccol0 = blockIdx.x * 64 + (tx << 2);
    float4 bi4 = *(const float4*)&bi[ccol0];
#pragma unroll
    for (int i = 0; i < 4; i++) {
        if (crow0 + i < M) {
            float4 o;
            o.x = acc[i][0] + bi4.x;
            o.y = acc[i][1] + bi4.y;
            o.z = acc[i][2] + bi4.z;
            o.w = acc[i][3] + bi4.w;
            *(float4*)&C[(long)(crow0 + i) * N + ccol0] = o;
        }
    }
}

// ---------------------------------------------------------------------------
__device__ __forceinline__ void block_ln_stats(float s, float q, float* mean, float* ri) {
    __shared__ float sh[8];
    int lane = threadIdx.x & 31, wid = threadIdx.x >> 5;
#pragma unroll
    for (int off = 16; off; off >>= 1) {
        s += __shfl_xor_sync(~0u, s, off);
        q += __shfl_xor_sync(~0u, q, off);
    }
    if (lane == 0) { sh[wid] = s; sh[4 + wid] = q; }
    __syncthreads();
    if (threadIdx.x == 0) {
        float S = sh[0] + sh[1] + sh[2] + sh[3];
        float Q = sh[4] + sh[5] + sh[6] + sh[7];
        float m = S * (1.f / 512.f);
        float v = Q * (1.f / 512.f) - m * m;
        sh[0] = m;
        sh[1] = rsqrtf(v + 1e-6f);
    }
    __syncthreads();
    *mean = sh[0];
    *ri   = sh[1];
}

// LN(x) * (1+sc_a) + sh_a   -> nbuf
__global__ void k_modln(const float* __restrict__ inp, int istream, int len, long tokOff) {
    int row = blockIdx.x;            // 0..B*len-1
    int b = row / len;
    int tid = threadIdx.x;           // 128
    float4 v = *(const float4*)&inp[(long)row * DM + tid * 4];
    float s = v.x + v.y + v.z + v.w;
    float q = v.x * v.x + v.y * v.y + v.z * v.z + v.w * v.w;
    float mean, ri;
    block_ln_stats(s, q, &mean, &ri);
    const float* ada = d_arena + OFF_ADA + ((long)istream * BB + b) * 3072;
    float4 sc = *(const float4*)&ada[512 + tid * 4];
    float4 shv = *(const float4*)&ada[tid * 4];
    float4 o;
    o.x = (v.x - mean) * ri * (1.f + sc.x) + shv.x;
    o.y = (v.y - mean) * ri * (1.f + sc.y) + shv.y;
    o.z = (v.z - mean) * ri * (1.f + sc.z) + shv.z;
    o.w = (v.w - mean) * ri * (1.f + sc.w) + shv.w;
    *(float4*)&d_arena[OFF_NBUF + (tokOff + row) * DM + tid * 4] = o;
}

// ---------------------------------------------------------------------------
// qkv raw -> per-head RMS norm, RoPE-xpos (motion) / learned pos (text),
// scatter to [B,H,L,64] layout.  One warp per (b,l,h); lane owns d and d+32.
__global__ void k_qkvx(const float* __restrict__ gqk,
                       const float* __restrict__ pos_q,
                       const float* __restrict__ pos_k) {
    int w = threadIdx.x >> 5;
    int lane = threadIdx.x & 31;
    int g = blockIdx.x * 4 + w;              // exactly BB*LL*NH warps
    int h = g & 7;
    int bl = g >> 3;
    int l = bl % LL;
    int b = bl / LL;

    int istream, t;
    long r;
    if (l < TT)            { istream = 2; t = l;            r = (long)b * TT + t; }
    else if (l < TT + SSRC){ istream = 1; t = l - TT;       r = 1232 + (long)b * SSRC + t; }
    else                   { istream = 0; t = l - TT - SSRC; r = 6032 + (long)b * NHID + t; }

    long base = r * DM + h * HD;
    float q0 = d_arena[OFF_QKV + base + lane];
    float q1 = d_arena[OFF_QKV + base + lane + 32];
    float k0 = d_arena[OFF_QKV + (long)TOKS * DM + base + lane];
    float k1 = d_arena[OFF_QKV + (long)TOKS * DM + base + lane + 32];
    float v0 = d_arena[OFF_QKV + 2L * TOKS * DM + base + lane];
    float v1 = d_arena[OFF_QKV + 2L * TOKS * DM + base + lane + 32];

    float sq = q0 * q0 + q1 * q1;
    float sk = k0 * k0 + k1 * k1;
#pragma unroll
    for (int off = 16; off; off >>= 1) {
        sq += __shfl_xor_sync(~0u, sq, off);
        sk += __shfl_xor_sync(~0u, sk, off);
    }
    float rq = rsqrtf(sq * (1.f / 64.f) + 1e-6f);
    float rk = rsqrtf(sk * (1.f / 64.f) + 1e-6f);
    q0 *= rq * gqk[(istream * 2 + 0) * 64 + lane];
    q1 *= rq * gqk[(istream * 2 + 0) * 64 + lane + 32];
    k0 *= rk * gqk[(istream * 2 + 1) * 64 + lane];
    k1 *= rk * gqk[(istream * 2 + 1) * 64 + lane + 32];

    if (istream == 2) {
        q0 += pos_q[t * 64 + lane];
        q1 += pos_q[t * 64 + lane + 32];
        k0 += pos_k[t * 64 + lane];
        k1 += pos_k[t * 64 + lane + 32];
    } else {
        // rotate_half partners: value at d^1 (same slot, lane^1)
        float rq0 = __shfl_xor_sync(~0u, q0, 1);
        float rq1 = __shfl_xor_sync(~0u, q1, 1);
        float rk0 = __shfl_xor_sync(~0u, k0, 1);
        float rk1 = __shfl_xor_sync(~0u, k1, 1);
        float tf = (float)t;
        float pw = (tf - 150.f) * (1.f / 512.f);
        // slot 0: d = lane
        {
            int d = lane, ii = d >> 1;
            float inv = powf(10000.f, -(float)(2 * ii) * (1.f / 64.f));
            float ang = tf * inv;
            float c = cosf(ang), s = sinf(ang);
            float scl = powf(((float)(2 * ii) + 25.6f) * (1.f / 89.6f), pw);
            float rotq = (d & 1) ? rq0 : -rq0;
            float rotk = (d & 1) ? rk0 : -rk0;
            float csq = c * scl, snq = s * scl;
            float csk = c / scl, snk = s / scl;
            q0 = q0 * csq + rotq * snq;
            k0 = k0 * csk + rotk * snk;
        }
        // slot 1: d = lane + 32
        {
            int d = lane + 32, ii = d >> 1;
            float inv = powf(10000.f, -(float)(2 * ii) * (1.f / 64.f));
            float ang = tf * inv;
            float c = cosf(ang), s = sinf(ang);
            float scl = powf(((float)(2 * ii) + 25.6f) * (1.f / 89.6f), pw);
            float rotq = (d & 1) ? rq1 : -rq1;
            float rotk = (d & 1) ? rk1 : -rk1;
            float csq = c * scl, snq = s * scl;
            float csk = c / scl, snk = s / scl;
            q1 = q1 * csq + rotq * snq;
            k1 = k1 * csk + rotk * snk;
        }
    }

    long o = (((long)(b * NH + h)) * LL + l) * HD;
    d_arena[OFF_QA + o + lane]      = q0;
    d_arena[OFF_QA + o + lane + 32] = q1;
    d_arena[OFF_KA + o + lane]      = k0;
    d_arena[OFF_KA + o + lane + 32] = k1;
    d_arena[OFF_VA + o + lane]      = v0;
    d_arena[OFF_VA + o + lane + 32] = v1;
}

// ---------------------------------------------------------------------------
// flash attention: block = 4 warps = 4 queries for one (b,h); 32-key tiles.
// Writes directly into the gathered token-major layout (OGAT).
#define QTILES 170   // ceil(677/4)
__global__ void k_attn(const int* __restrict__ valid) {
    __shared__ float Qs[4][64];
    __shared__ float Ks[32][65];
    __shared__ float Vs[32][64];
    __shared__ int   sVal[LL];

    int tid = threadIdx.x;
    int w = tid >> 5, lane = tid & 31;
    int bh = blockIdx.x / QTILES;
    int qt = blockIdx.x % QTILES;
    int b = bh >> 3, h = bh & 7;
    int l = qt * 4 + w;
    bool qok = l < LL;

    for (int m = tid; m < LL; m += 128) sVal[m] = valid[b * LL + m];

    long hbase = (long)bh * LL * HD;
    if (qok) {
        Qs[w][lane]      = d_arena[OFF_QA + hbase + (long)l * HD + lane];
        Qs[w][lane + 32] = d_arena[OFF_QA + hbase + (long)l * HD + lane + 32];
    }
    __syncthreads();
    int qv = qok ? sVal[l] : 0;

    float mrun = -INFINITY, lrun = 0.f, o0 = 0.f, o1 = 0.f;

    for (int kb = 0; kb < LL; kb += 32) {
        for (int e = tid; e < 512; e += 128) {   // 32 keys * 16 float4
            int j = e >> 4;
            int d4 = (e & 15) << 2;
            float4 kv = make_float4(0.f, 0.f, 0.f, 0.f);
            float4 vv = kv;
            int m = kb + j;
            if (m < LL) {
                long p = hbase + (long)m * HD + d4;
                kv = *(const float4*)&d_arena[OFF_KA + p];
                vv = *(const float4*)&d_arena[OFF_VA + p];
            }
            Ks[j][d4 + 0] = kv.x; Ks[j][d4 + 1] = kv.y;
            Ks[j][d4 + 2] = kv.z; Ks[j][d4 + 3] = kv.w;
            *(float4*)&Vs[j][d4] = vv;
        }
        __syncthreads();

        if (qok) {
            int m = kb + lane;
            float acc = 0.f;
#pragma unroll
            for (int d = 0; d < 64; d += 4) {
                acc += Qs[w][d] * Ks[lane][d]
                     + Qs[w][d + 1] * Ks[lane][d + 1]
                     + Qs[w][d + 2] * Ks[lane][d + 2]
                     + Qs[w][d + 3] * Ks[lane][d + 3];
            }
            bool ok = (m < LL) && (((qv != 0) && (sVal[m] != 0)) || (m == l));
            float sc = ok ? acc * 0.125f : -INFINITY;

            float mt = sc;
#pragma unroll
            for (int off = 16; off; off >>= 1) mt = fmaxf(mt, __shfl_xor_sync(~0u, mt, off));
            float nm = fmaxf(mrun, mt);
            if (nm > -INFINITY) {
                float corr = __expf(mrun - nm);
                lrun *= corr; o0 *= corr; o1 *= corr;
                float p = (sc > -INFINITY) ? __expf(sc - nm) : 0.f;
                float ps = p;
#pragma unroll
                for (int off = 16; off; off >>= 1) ps += __shfl_xor_sync(~0u, ps, off);
                lrun += ps;
#pragma unroll
                for (int j = 0; j < 32; j++) {
                    float pj = __shfl_sync(~0u, p, j);
                    o0 += pj * Vs[j][lane];
                    o1 += pj * Vs[j][lane + 32];
                }
                mrun = nm;
            }
        }
        __syncthreads();
    }

    if (qok) {
        float inv = 1.f / lrun;
        int rr;
        if (l < TT)             rr = b * TT + l;
        else if (l < TT + SSRC) rr = 1232 + b * SSRC + (l - TT);
        else                    rr = 6032 + b * NHID + (l - TT - SSRC);
        long op = (long)rr * DM + h * HD;
        d_arena[OFF_OGAT + op + lane]      = o0 * inv;
        d_arena[OFF_OGAT + op + lane + 32] = o1 * inv;
    }
}

// ---------------------------------------------------------------------------
// h = x + g_a * a ; n2 = LN(h)*(1+sc_m)+sh_m
__global__ void k_resln(const float* __restrict__ inp, int istream, int len, long tokOff) {
    int row = blockIdx.x;
    int b = row / len;
    int tid = threadIdx.x;
    long rb = (tokOff + row) * (long)DM;
    const float* ada = d_arena + OFF_ADA + ((long)istream * BB + b) * 3072;

    float4 x4 = *(const float4*)&inp[(long)row * DM + tid * 4];
    float4 a4 = *(const float4*)&d_arena[OFF_ABUF + rb + tid * 4];
    float4 g4 = *(const float4*)&ada[1024 + tid * 4];
    float4 hv;
    hv.x = x4.x + g4.x * a4.x;
    hv.y = x4.y + g4.y * a4.y;
    hv.z = x4.z + g4.z * a4.z;
    hv.w = x4.w + g4.w * a4.w;
    *(float4*)&d_arena[OFF_HBUF + rb + tid * 4] = hv;

    float s = hv.x + hv.y + hv.z + hv.w;
    float q = hv.x * hv.x + hv.y * hv.y + hv.z * hv.z + hv.w * hv.w;
    float mean, ri;
    block_ln_stats(s, q, &mean, &ri);
    float4 sc = *(const float4*)&ada[2048 + tid * 4];
    float4 shv = *(const float4*)&ada[1536 + tid * 4];
    float4 o;
    o.x = (hv.x - mean) * ri * (1.f + sc.x) + shv.x;
    o.y = (hv.y - mean) * ri * (1.f + sc.y) + shv.y;
    o.z = (hv.z - mean) * ri * (1.f + sc.z) + shv.z;
    o.w = (hv.w - mean) * ri * (1.f + sc.w) + shv.w;
    *(float4*)&d_arena[OFF_N2 + rb + tid * 4] = o;
}

// ---------------------------------------------------------------------------
// g = lin * gelu_exact(gate)
__global__ void k_geglu() {
    long idx = (long)blockIdx.x * blockDim.x + threadIdx.x;  // TOKS*512 float4 units
    if (idx >= (long)TOKS * 512) return;
    long rrow = idx >> 9;
    int j4 = (int)(idx & 511) << 2;
    float4 lin = *(const float4*)&d_arena[OFF_U + rrow * 4096 + j4];
    float4 gt  = *(const float4*)&d_arena[OFF_U + rrow * 4096 + 2048 + j4];
    float4 o;
    o.x = lin.x * (0.5f * gt.x * (1.f + erff(gt.x * 0.7071067811865475f)));
    o.y = lin.y * (0.5f * gt.y * (1.f + erff(gt.y * 0.7071067811865475f)));
    o.z = lin.z * (0.5f * gt.z * (1.f + erff(gt.z * 0.7071067811865475f)));
    o.w = lin.w * (0.5f * gt.w * (1.f + erff(gt.w * 0.7071067811865475f)));
    *(float4*)&d_arena[OFF_G + rrow * 2048 + j4] = o;
}

// ---------------------------------------------------------------------------
// out = h + g_m * ff, scattered to concat layout [txt, src, hid]
__global__ void k_final(float* __restrict__ out, int istream, int len, long tokOff, int catOff) {
    int row = blockIdx.x;
    int b = row / len;
    int t = row % len;
    int tid = threadIdx.x;
    long rb = (tokOff + row) * (long)DM;
    const float* ada = d_arena + OFF_ADA + ((long)istream * BB + b) * 3072;
    float4 hv = *(const float4*)&d_arena[OFF_HBUF + rb + tid * 4];
    float4 fv = *(const float4*)&d_arena[OFF_FF + rb + tid * 4];
    float4 gm = *(const float4*)&ada[2560 + tid * 4];
    float4 o;
    o.x = hv.x + gm.x * fv.x;
    o.y = hv.y + gm.y * fv.y;
    o.z = hv.z + gm.z * fv.z;
    o.w = hv.w + gm.w * fv.w;
    *(float4*)&out[((long)b * LL + catOff + t) * DM + tid * 4] = o;
}

// ---------------------------------------------------------------------------
extern "C" void kernel_launch(void* const* d_in, const int* in_sizes, int n_in,
                              void* d_out, int out_size) {
    const float* x     = (const float*)d_in[0];
    const float* src   = (const float*)d_in[1];
    const float* txt   = (const float*)d_in[2];
    const float* temb  = (const float*)d_in[3];
    const float* Wqkv  = (const float*)d_in[4];
    const float* bqkv  = (const float*)d_in[5];
    const float* Wo    = (const float*)d_in[6];
    const float* bo    = (const float*)d_in[7];
    const float* gqk   = (const float*)d_in[8];
    const float* Wada  = (const float*)d_in[9];
    const float* bada  = (const float*)d_in[10];
    const float* Wff1  = (const float*)d_in[11];
    const float* bff1  = (const float*)d_in[12];
    const float* Wff2  = (const float*)d_in[13];
    const float* bff2  = (const float*)d_in[14];
    const float* pos_q = (const float*)d_in[15];
    const float* pos_k = (const float*)d_in[16];
    const int*   valid = (const int*)d_in[17];
    float* out = (float*)d_out;

    // ref-stream metadata: i=0 hidden(x), i=1 src, i=2 txt
    const int  lens[3]    = {NHID, SSRC, TT};
    const long tokOffs[3] = {6032, 1232, 0};
    const int  catOffs[3] = {377, 77, 0};
    const float* inps[3]  = {x, src, txt};

    // 1. silu(temb)
    k_silu<<<(BB * DM + 255) / 256, 256>>>(temb);

    // 2. ada = st @ Wada[s] + bada[s]
    {
        dim3 g(3072 / 64, 1, 3);
        k_gemm<<<g, 256>>>(Wada, bada, OFF_ST, OFF_ADA, BB, 3072, DM,
                           512L * 3072, 3072L, 16L * 3072);
    }

    // 3. modulated LN per stream
    for (int i = 0; i < 3; i++)
        k_modln<<<BB * lens[i], 128>>>(inps[i], i, lens[i], tokOffs[i]);

    // 4. QKV GEMMs (z over q,k,v)
    for (int i = 0; i < 3; i++) {
        int M = BB * lens[i];
        dim3 g(DM / 64, (M + 63) / 64, 3);
        k_gemm<<<g, 256>>>(Wqkv + (long)i * 3 * DM * DM, bqkv + (long)i * 3 * DM,
                           OFF_NBUF + tokOffs[i] * DM, OFF_QKV + tokOffs[i] * DM,
                           M, DM, DM, (long)DM * DM, (long)DM, (long)TOKS * DM);
    }

    // 5. RMS + RoPE/pos, scatter to [B,H,L,64]
    k_qkvx<<<(BB * LL * NH) / 4, 128>>>(gqk, pos_q, pos_k);

    // 6. attention
    k_attn<<<BB * NH * QTILES, 128>>>(valid);

    // 7. output projection
    for (int i = 0; i < 3; i++) {
        int M = BB * lens[i];
        dim3 g(DM / 64, (M + 63) / 64, 1);
        k_gemm<<<g, 256>>>(Wo + (long)i * DM * DM, bo + (long)i * DM,
                           OFF_OGAT + tokOffs[i] * DM, OFF_ABUF + tokOffs[i] * DM,
                           M, DM, DM, 0, 0, 0);
    }

    // 8. residual + LN2 (modulated)
    for (int i = 0; i < 3; i++)
        k_resln<<<BB * lens[i], 128>>>(inps[i], i, lens[i], tokOffs[i]);

    // 9. FF1
    for (int i = 0; i < 3; i++) {
        int M = BB * lens[i];
        dim3 g(4096 / 64, (M + 63) / 64, 1);
        k_gemm<<<g, 256>>>(Wff1 + (long)i * DM * 4096, bff1 + (long)i * 4096,
                           OFF_N2 + tokOffs[i] * DM, OFF_U + tokOffs[i] * 4096,
                           M, 4096, DM, 0, 0, 0);
    }

    // 10. GeGLU gate
    k_geglu<<<(int)(((long)TOKS * 512 + 255) / 256), 256>>>();

    // 11. FF2
    for (int i = 0; i < 3; i++) {
        int M = BB * lens[i];
        dim3 g(DM / 64, (M + 63) / 64, 1);
        k_gemm<<<g, 256>>>(Wff2 + (long)i * 2048 * DM, bff2 + (long)i * DM,
                           OFF_G + tokOffs[i] * 2048, OFF_FF + tokOffs[i] * DM,
                           M, DM, 2048, 0, 0, 0);
    }

    // 12. final residual + scatter to output concat layout
    for (int i = 0; i < 3; i++)
        k_final<<<BB * lens[i], 128>>>(out, i, lens[i], tokOffs[i], catOffs[i]);
}